// round 8
// baseline (speedup 1.0000x reference)
#include <cuda_runtime.h>

// Persistent LSTM: B=128, T=365, D=32, H=512, fp32, out[b,t,:]=h_t.
// 128 CTAs x 512 threads (4 warp-groups of 4 warps). CTA tile 32 batch x 16
// units. Dataflow exchange: NO global barrier. h split into 4 chunks of 128
// k-values; per-producer flags + per-chunk mbarrier/cp.async.bulk(16KB).
// Warp-group q consumes exactly chunk q (split-K aligned with exchange
// chunks) + 8 private x-columns (136 k each). Copies for step t+1 are issued
// right after step t's last sync, overlapping the epilogue/flag window.
// Inner product: packed fma.rn.f32x2, gate pairs (i,f),(g,o).

#define B_   128
#define T_   365
#define D_   32
#define H_   512
#define G4   2048
#define KTOT 544
#define NCTA 128
#define NTHR 512
#define WPITCH 548

// smem floats: [mbar 8][W 64*548][A 544*32][red 2*1280 u64]
#define SW_OFF   8
#define SW_FLOATS (64 * WPITCH)            // 35072
#define SA_OFF   (SW_OFF + SW_FLOATS)      // 35080
#define SA_FLOATS (KTOT * 32)              // 17408
#define RED_OFF  (SA_OFF + SA_FLOATS)      // 52488
#define RED_PITCH 10                       // u64 per slot
#define SMEM_BYTES ((RED_OFF * 4) + 2 * 128 * RED_PITCH * 8)   // 230432

__device__ float g_hT[2][4][512][32];      // [parity][mb][unit][m-local]
__device__ unsigned int g_flags[4][32];    // [mb][ub] = steps completed

__global__ void init_flags_kernel() {
    if (threadIdx.x < 128) ((unsigned int*)g_flags)[threadIdx.x] = 0u;
}

__device__ __forceinline__ unsigned long long pack2(float v) {
    unsigned long long r;
    asm("mov.b64 %0, {%1, %1};" : "=l"(r) : "f"(v));
    return r;
}
__device__ __forceinline__ void ffma2(unsigned long long& d,
                                      unsigned long long a,
                                      unsigned long long b) {
    asm("fma.rn.f32x2 %0, %1, %2, %0;" : "+l"(d) : "l"(a), "l"(b));
}
__device__ __forceinline__ void fadd2(unsigned long long& d, unsigned long long a) {
    asm("add.rn.f32x2 %0, %0, %1;" : "+l"(d) : "l"(a));
}
__device__ __forceinline__ void unpack2(unsigned long long v, float& lo, float& hi) {
    asm("mov.b64 {%0, %1}, %2;" : "=f"(lo), "=f"(hi) : "l"(v));
}
__device__ __forceinline__ float fsig(float z) {
    return 1.0f / (1.0f + __expf(-z));
}
__device__ __forceinline__ float ftanh_(float z) {
    return 1.0f - 2.0f / (__expf(2.0f * z) + 1.0f);
}
__device__ __forceinline__ unsigned int smem_u32(const void* p) {
    return (unsigned int)__cvta_generic_to_shared(p);
}
__device__ __forceinline__ void mbar_init(unsigned int mbar, unsigned int cnt) {
    asm volatile("mbarrier.init.shared.b64 [%0], %1;" :: "r"(mbar), "r"(cnt) : "memory");
}
__device__ __forceinline__ void mbar_expect_tx(unsigned int mbar, unsigned int bytes) {
    asm volatile("mbarrier.arrive.expect_tx.shared.b64 _, [%0], %1;"
                 :: "r"(mbar), "r"(bytes) : "memory");
}
__device__ __forceinline__ void bulk_g2s(unsigned int dst, const void* src,
                                         unsigned int bytes, unsigned int mbar) {
    asm volatile("cp.async.bulk.shared::cluster.global.mbarrier::complete_tx::bytes "
                 "[%0], [%1], %2, [%3];"
                 :: "r"(dst), "l"(src), "r"(bytes), "r"(mbar) : "memory");
}
__device__ __forceinline__ void mbar_wait(unsigned int mbar, unsigned int parity) {
    asm volatile(
        "{\n\t.reg .pred P1;\n\t"
        "WAIT_LOOP_%=:\n\t"
        "mbarrier.try_wait.parity.shared.b64 P1, [%0], %1;\n\t"
        "@P1 bra.uni WAIT_DONE_%=;\n\t"
        "bra.uni WAIT_LOOP_%=;\n\t"
        "WAIT_DONE_%=:\n\t}"
        :: "r"(mbar), "r"(parity) : "memory");
}
__device__ __forceinline__ unsigned int ld_acq(const unsigned int* p) {
    unsigned int v;
    asm volatile("ld.acquire.gpu.global.u32 %0, [%1];" : "=r"(v) : "l"(p));
    return v;
}
__device__ __forceinline__ void bar_named(int id) {
    asm volatile("bar.sync %0, 128;" :: "r"(id) : "memory");
}

__global__ __launch_bounds__(NTHR, 1) void lstm_persistent(
    const float* __restrict__ x,    // [B,T,D]
    const float* __restrict__ Wx,   // [D,4H]
    const float* __restrict__ Wh,   // [H,4H]
    const float* __restrict__ bias, // [4H]
    float* __restrict__ out)        // [B,T,H]
{
    extern __shared__ float smem[];
    float* sWT = smem + SW_OFF;                       // [64][WPITCH]
    float* sAT = smem + SA_OFF;                       // [544][32]
    unsigned long long* buf0 = (unsigned long long*)(smem + RED_OFF);
    unsigned long long* buf1 = buf0 + 128 * RED_PITCH;
    const unsigned int mbar0 = smem_u32(smem);        // 4 mbarriers, 8B each
    const unsigned int sATb  = smem_u32(sAT);

    const int tid  = threadIdx.x;
    const int warp = tid >> 5;
    const int lane = tid & 31;
    const int wm   = warp & 3;                 // m-subtile (rows 8wm..8wm+7)
    const int q    = warp >> 2;                // warp-group / k-chunk 0..3
    const int ub   = blockIdx.x & 31;
    const int mb   = blockIdx.x >> 5;
    const int j0   = ub * 16;
    const int m0   = mb * 32;
    const int u    = lane & 15;
    const int gA   = lane >> 4;
    const int j    = j0 + u;

    // ---- prologue ----
    if (tid == 0) {
        #pragma unroll
        for (int c = 0; c < 4; ++c) mbar_init(mbar0 + c * 8, 1);
    }
    for (int i = 0; i < (64 * KTOT) / NTHR; ++i) {   // W transposed
        int idx = i * NTHR + tid;
        int r = idx & 63;
        int k = idx >> 6;
        int col = (r >> 4) * H_ + j0 + (r & 15);
        float v = (k < H_) ? Wh[(size_t)k * G4 + col]
                           : Wx[(size_t)(k - H_) * G4 + col];
        sWT[r * WPITCH + k] = v;
    }
    {   // zero h region of A, stage x(0)
        float4 z4 = make_float4(0.f, 0.f, 0.f, 0.f);
        #pragma unroll
        for (int i = 0; i < 8; ++i)
            *(float4*)(sAT + (i * NTHR + tid) * 4) = z4;
        for (int e = tid; e < 1024; e += NTHR) {
            int d = e >> 5, m = e & 31;
            sAT[(512 + d) * 32 + m] = x[(size_t)(m0 + m) * (T_ * D_) + d];
        }
    }
    const float biasA = bias[gA * H_ + j];
    const float biasB = bias[(gA + 2) * H_ + j];
    float c_reg[8] = {0.f,0.f,0.f,0.f,0.f,0.f,0.f,0.f};
    __syncthreads();

    const float* wrA = sWT + lane * WPITCH;          // gate-col lane
    const float* wrB = wrA + 32 * WPITCH;            // gate-col lane+32
    const float* aQ  = sAT + (q * 128) * 32 + wm * 8;
    const float* aX  = sAT + (512 + 8 * q) * 32 + wm * 8;
    const int    kQ  = q * 128;
    const int    kX  = 512 + 8 * q;
    const int    slot = wm * 32 + lane;
    const unsigned int mbar_q = mbar0 + q * 8;

    for (int t = 0; t < T_; ++t) {
        if (t > 0) mbar_wait(mbar_q, (unsigned)((t - 1) & 1));

        // ---- k-loop: 128 h-k's + 8 x-k's, 8 m x 2 gate-cols per lane ----
        unsigned long long acc[4][2] = {};
        #pragma unroll 2
        for (int k4 = 0; k4 < 128; k4 += 4) {
            float4 wa = *(const float4*)(wrA + kQ + k4);
            float4 wb = *(const float4*)(wrB + kQ + k4);
            #pragma unroll
            for (int kk = 0; kk < 4; ++kk) {
                const float* arow = aQ + (k4 + kk) * 32;
                ulonglong2 a01 = *(const ulonglong2*)(arow);
                ulonglong2 a23 = *(const ulonglong2*)(arow + 4);
                float wak = (kk == 0) ? wa.x : (kk == 1) ? wa.y
                          : (kk == 2) ? wa.z : wa.w;
                float wbk = (kk == 0) ? wb.x : (kk == 1) ? wb.y
                          : (kk == 2) ? wb.z : wb.w;
                unsigned long long wa2 = pack2(wak);
                unsigned long long wb2 = pack2(wbk);
                ffma2(acc[0][0], a01.x, wa2); ffma2(acc[0][1], a01.x, wb2);
                ffma2(acc[1][0], a01.y, wa2); ffma2(acc[1][1], a01.y, wb2);
                ffma2(acc[2][0], a23.x, wa2); ffma2(acc[2][1], a23.x, wb2);
                ffma2(acc[3][0], a23.y, wa2); ffma2(acc[3][1], a23.y, wb2);
            }
        }
        #pragma unroll
        for (int k4 = 0; k4 < 8; k4 += 4) {          // x part
            float4 wa = *(const float4*)(wrA + kX + k4);
            float4 wb = *(const float4*)(wrB + kX + k4);
            #pragma unroll
            for (int kk = 0; kk < 4; ++kk) {
                const float* arow = aX + (k4 + kk) * 32;
                ulonglong2 a01 = *(const ulonglong2*)(arow);
                ulonglong2 a23 = *(const ulonglong2*)(arow + 4);
                float wak = (kk == 0) ? wa.x : (kk == 1) ? wa.y
                          : (kk == 2) ? wa.z : wa.w;
                float wbk = (kk == 0) ? wb.x : (kk == 1) ? wb.y
                          : (kk == 2) ? wb.z : wb.w;
                unsigned long long wa2 = pack2(wak);
                unsigned long long wb2 = pack2(wbk);
                ffma2(acc[0][0], a01.x, wa2); ffma2(acc[0][1], a01.x, wb2);
                ffma2(acc[1][0], a01.y, wa2); ffma2(acc[1][1], a01.y, wb2);
                ffma2(acc[2][0], a23.x, wa2); ffma2(acc[2][1], a23.x, wb2);
                ffma2(acc[3][0], a23.y, wa2); ffma2(acc[3][1], a23.y, wb2);
            }
        }

        // ---- split-K reduce: g1->buf0, g3->buf1; g0+=buf0; g2+=buf1->buf1;
        //      g0+=buf1 ----
        if (q == 1) {
            unsigned long long* d0 = buf0 + (size_t)slot * RED_PITCH;
            #pragma unroll
            for (int p = 0; p < 4; ++p)
                *(ulonglong2*)(d0 + 2 * p) = make_ulonglong2(acc[p][0], acc[p][1]);
        }
        if (q == 3) {
            unsigned long long* d1 = buf1 + (size_t)slot * RED_PITCH;
            #pragma unroll
            for (int p = 0; p < 4; ++p)
                *(ulonglong2*)(d1 + 2 * p) = make_ulonglong2(acc[p][0], acc[p][1]);
        }
        __syncthreads();
        if (q == 0) {
            const unsigned long long* s0 = buf0 + (size_t)slot * RED_PITCH;
            #pragma unroll
            for (int p = 0; p < 4; ++p) {
                ulonglong2 v = *(const ulonglong2*)(s0 + 2 * p);
                fadd2(acc[p][0], v.x); fadd2(acc[p][1], v.y);
            }
        }
        if (q == 2) {
            unsigned long long* s1 = buf1 + (size_t)slot * RED_PITCH;
            #pragma unroll
            for (int p = 0; p < 4; ++p) {
                ulonglong2 v = *(const ulonglong2*)(s1 + 2 * p);
                fadd2(acc[p][0], v.x); fadd2(acc[p][1], v.y);
                *(ulonglong2*)(s1 + 2 * p) = make_ulonglong2(acc[p][0], acc[p][1]);
            }
        }
        __syncthreads();

        if (q == 0) {
            const unsigned long long* s1 = buf1 + (size_t)slot * RED_PITCH;
            #pragma unroll
            for (int p = 0; p < 4; ++p) {
                ulonglong2 v = *(const ulonglong2*)(s1 + 2 * p);
                fadd2(acc[p][0], v.x); fadd2(acc[p][1], v.y);
            }
            // prefetch own x slice (d 0..7) for t+1
            if (t + 1 < T_) {
                for (int e = tid; e < 256; e += 128) {
                    int d = e >> 5, m = e & 31;
                    sAT[(512 + d) * 32 + m] =
                        x[(size_t)(m0 + m) * (T_ * D_) + (size_t)(t + 1) * D_ + d];
                }
            }
            // ---- epilogue ----
            float zA[8], zB[8];
            #pragma unroll
            for (int p = 0; p < 4; ++p) {
                unpack2(acc[p][0], zA[2 * p], zA[2 * p + 1]);
                unpack2(acc[p][1], zB[2 * p], zB[2 * p + 1]);
            }
            float v[8];
            if (lane < 16) {
                #pragma unroll
                for (int r = 0; r < 8; ++r)
                    v[r] = fsig(zA[r] + biasA) * ftanh_(zB[r] + biasB);
            }
            #pragma unroll
            for (int r = 0; r < 8; ++r)
                v[r] = __shfl_sync(0xffffffffu, v[r], lane ^ 16);
            if (lane >= 16) {
                float h[8];
                #pragma unroll
                for (int r = 0; r < 8; ++r) {
                    float cn = fsig(zA[r] + biasA) * c_reg[r] + v[r];
                    c_reg[r] = cn;
                    h[r] = fsig(zB[r] + biasB) * ftanh_(cn);
                    out[(size_t)(m0 + wm * 8 + r) * ((size_t)T_ * H_) +
                        (size_t)t * H_ + j] = h[r];
                }
                float* hdst = &g_hT[t & 1][mb][j][wm * 8];
                *(float4*)(hdst)     = make_float4(h[0], h[1], h[2], h[3]);
                *(float4*)(hdst + 4) = make_float4(h[4], h[5], h[6], h[7]);
            }
            bar_named(1);                              // group 0, 128 threads
            if (tid == 0) {
                __threadfence();                       // h -> visible before flag
                g_flags[mb][ub] = (unsigned)(t + 1);
            }
            if (wm == 0 && t + 1 < T_) {               // warp 0: chunk 0 copy
                unsigned tgt = (unsigned)(t + 1);
                while (!__all_sync(0xffffffffu,
                        lane >= 8 || ld_acq(&g_flags[mb][lane]) >= tgt)) { }
                if (lane == 0) {
                    mbar_expect_tx(mbar_q, 16384u);
                    bulk_g2s(sATb, &g_hT[t & 1][mb][0][0], 16384u, mbar_q);
                }
            }
        } else {
            if (t + 1 < T_) {
                // prefetch own x slice (d 8q..8q+7) for t+1
                for (int e = (tid & 127); e < 256; e += 128) {
                    int d = e >> 5, m = e & 31;
                    sAT[(512 + 8 * q + d) * 32 + m] =
                        x[(size_t)(m0 + m) * (T_ * D_) +
                          (size_t)(t + 1) * D_ + (8 * q + d)];
                }
                bar_named(q + 1);                      // order STS vs next k-loop
                if (wm == 0) {                         // warp 4q: chunk q copy
                    unsigned tgt = (unsigned)(t + 1);
                    while (!__all_sync(0xffffffffu,
                            lane >= 8 ||
                            ld_acq(&g_flags[mb][8 * q + lane]) >= tgt)) { }
                    if (lane == 0) {
                        mbar_expect_tx(mbar_q, 16384u);
                        bulk_g2s(sATb + (unsigned)(q * 16384),
                                 &g_hT[t & 1][mb][128 * q][0], 16384u, mbar_q);
                    }
                }
            }
        }
    }
}

extern "C" void kernel_launch(void* const* d_in, const int* in_sizes, int n_in,
                              void* d_out, int out_size) {
    const float* x  = (const float*)d_in[0];
    const float* Wx = (const float*)d_in[1];
    const float* Wh = (const float*)d_in[2];
    const float* b  = (const float*)d_in[3];
    float* out = (float*)d_out;

    static bool attr_set = false;
    if (!attr_set) {
        cudaFuncSetAttribute(lstm_persistent,
                             cudaFuncAttributeMaxDynamicSharedMemorySize,
                             SMEM_BYTES);
        attr_set = true;
    }

    init_flags_kernel<<<1, 128>>>();
    lstm_persistent<<<NCTA, NTHR, SMEM_BYTES>>>(x, Wx, Wh, b, out);
}

// round 10
// speedup vs baseline: 1.0473x; 1.0473x over previous
#include <cuda_runtime.h>

// Persistent LSTM: B=128, T=365, D=32, H=512, fp32, out[b,t,:]=h_t.
// R6 skeleton: 128 CTAs x 256 threads (8 warps), CTA tile 32 batch x 16
// units, 2-way split-K (warps 0-3: k[0,272), warps 4-7: k[272,544)).
// W resident transposed sWT[gatecol][k] (pitch 548); A transposed sAT[k][m].
// R10 = R9 with RED_PITCH fixed to 10 (16B-aligned ulonglong2 slots):
// (1) flag-array barrier (coalesced 32-lane acquire-poll, no atomics);
// (2) h staging split into halves, each released by its own named barrier;
// (3) x(t+1) prefetched by kh1 warps during kh0's epilogue.

#define B_   128
#define T_   365
#define D_   32
#define H_   512
#define G4   2048
#define KTOT 544
#define KSPL 272
#define NCTA 128
#define NTHR 256
#define WPITCH 548

// smem floats: [W 64*548][A 544*32][red 128*10 u64]
#define SW_FLOATS (64 * WPITCH)            // 35072
#define SA_OFF    SW_FLOATS
#define SA_FLOATS (KTOT * 32)              // 17408
#define RED_OFF   (SA_OFF + SA_FLOATS)     // 52480
#define RED_PITCH 10                       // u64/slot; 80B = 16B-aligned
#define SMEM_BYTES (RED_OFF * 4 + 128 * RED_PITCH * 8)   // 220160

__device__ float g_hT[2][4][512][32];      // [parity][mb][unit][m-local]
__device__ unsigned int g_flags[4][32];    // [mb][ub] = steps completed

__global__ void init_flags_kernel() {
    if (threadIdx.x < 128) ((unsigned int*)g_flags)[threadIdx.x] = 0u;
}

__device__ __forceinline__ unsigned long long pack2(float v) {
    unsigned long long r;
    asm("mov.b64 %0, {%1, %1};" : "=l"(r) : "f"(v));
    return r;
}
__device__ __forceinline__ void ffma2(unsigned long long& d,
                                      unsigned long long a,
                                      unsigned long long b) {
    asm("fma.rn.f32x2 %0, %1, %2, %0;" : "+l"(d) : "l"(a), "l"(b));
}
__device__ __forceinline__ void fadd2(unsigned long long& d, unsigned long long a) {
    asm("add.rn.f32x2 %0, %0, %1;" : "+l"(d) : "l"(a));
}
__device__ __forceinline__ void unpack2(unsigned long long v, float& lo, float& hi) {
    asm("mov.b64 {%0, %1}, %2;" : "=f"(lo), "=f"(hi) : "l"(v));
}
__device__ __forceinline__ float fsig(float z) {
    return 1.0f / (1.0f + __expf(-z));
}
__device__ __forceinline__ float ftanh_(float z) {
    return 1.0f - 2.0f / (__expf(2.0f * z) + 1.0f);
}
__device__ __forceinline__ void cp_async16(unsigned int smem_dst, const void* gsrc) {
    asm volatile("cp.async.cg.shared.global [%0], [%1], 16;"
                 :: "r"(smem_dst), "l"(gsrc) : "memory");
}
__device__ __forceinline__ void cp_async_wait_all() {
    asm volatile("cp.async.commit_group;\n\tcp.async.wait_group 0;" ::: "memory");
}
__device__ __forceinline__ unsigned int smem_u32(const void* p) {
    return (unsigned int)__cvta_generic_to_shared(p);
}
__device__ __forceinline__ unsigned int ld_acq(const unsigned int* p) {
    unsigned int v;
    asm volatile("ld.acquire.gpu.global.u32 %0, [%1];" : "=r"(v) : "l"(p));
    return v;
}
__device__ __forceinline__ void st_rel(unsigned int* p, unsigned int v) {
    asm volatile("st.release.gpu.global.u32 [%0], %1;" :: "l"(p), "r"(v) : "memory");
}
__device__ __forceinline__ void bar_named(int id) {
    asm volatile("bar.sync %0, 128;" :: "r"(id) : "memory");
}

__global__ __launch_bounds__(NTHR, 1) void lstm_persistent(
    const float* __restrict__ x,    // [B,T,D]
    const float* __restrict__ Wx,   // [D,4H]
    const float* __restrict__ Wh,   // [H,4H]
    const float* __restrict__ bias, // [4H]
    float* __restrict__ out)        // [B,T,H]
{
    extern __shared__ float smem[];
    float* sWT = smem;                                // [64][WPITCH]
    float* sAT = smem + SA_OFF;                       // [544][32]
    unsigned long long* sRed = (unsigned long long*)(smem + RED_OFF);
    const unsigned int sATb = smem_u32(sAT);

    const int tid  = threadIdx.x;
    const int warp = tid >> 5;
    const int lane = tid & 31;
    const int wm   = warp & 3;                 // m-subtile (rows 8wm..8wm+7)
    const int kh   = warp >> 2;                // k-half 0/1
    const int ub   = blockIdx.x & 31;
    const int mb   = blockIdx.x >> 5;
    const int j0   = ub * 16;
    const int m0   = mb * 32;
    const int u    = lane & 15;
    const int gA   = lane >> 4;
    const int j    = j0 + u;

    // ---- prologue: W transposed; zero h region; stage x(0) ----
    for (int i = 0; i < (64 * KTOT) / NTHR; ++i) {    // 136 iters
        int idx = i * NTHR + tid;
        int r = idx & 63;
        int k = idx >> 6;
        int col = (r >> 4) * H_ + j0 + (r & 15);
        float v = (k < H_) ? Wh[(size_t)k * G4 + col]
                           : Wx[(size_t)(k - H_) * G4 + col];
        sWT[r * WPITCH + k] = v;
    }
    {
        float4 z4 = make_float4(0.f, 0.f, 0.f, 0.f);
        #pragma unroll
        for (int i = 0; i < 16; ++i)                  // rows [0,512): 4096 f4
            *(float4*)(sAT + (i * NTHR + tid) * 4) = z4;
        int d = tid & 31, mg = tid >> 5;              // x(0): coalesced LDG
        #pragma unroll
        for (int rr = 0; rr < 4; ++rr) {
            int m = mg + rr * 8;
            sAT[(512 + d) * 32 + m] = x[(size_t)(m0 + m) * (T_ * D_) + d];
        }
    }
    const float biasA = bias[gA * H_ + j];
    const float biasB = bias[(gA + 2) * H_ + j];
    float c_reg[8] = {0.f,0.f,0.f,0.f,0.f,0.f,0.f,0.f};
    __syncthreads();

    const float* wrA = sWT + lane * WPITCH + kh * KSPL;
    const float* wrB = wrA + 32 * WPITCH;
    const float* aB  = sAT + kh * KSPL * 32 + wm * 8;
    const int slot = wm * 32 + lane;

    for (int t = 0; t < T_; ++t) {
        if (t > 0) {
            // flag barrier: warp 0 polls all 32 producer flags (coalesced)
            if (warp == 0) {
                while (!__all_sync(0xffffffffu,
                        ld_acq(&g_flags[mb][lane]) >= (unsigned)t)) { }
            }
            __syncthreads();

            // stage h halves; each half released by its own named barrier
            const float* hsrc = &g_hT[(t - 1) & 1][mb][0][0];
            int half = tid >> 7;                      // 0: f4 [0,2176)=k[0,272)
            int lt   = tid & 127;                     // 1: f4 [2176,4096)
            if (half == 0) {
                #pragma unroll
                for (int i = 0; i < 17; ++i) {
                    int f4 = i * 128 + lt;
                    cp_async16(sATb + (unsigned)f4 * 16, hsrc + (size_t)f4 * 4);
                }
            } else {
                #pragma unroll
                for (int i = 0; i < 15; ++i) {
                    int f4 = 2176 + i * 128 + lt;
                    cp_async16(sATb + (unsigned)f4 * 16, hsrc + (size_t)f4 * 4);
                }
            }
            cp_async_wait_all();
            bar_named(1 + half);
        }

        // ---- k-loop (half range): 8 m x 2 gate-col rows per lane ----
        unsigned long long acc[4][2] = {};
        #pragma unroll 2
        for (int k4 = 0; k4 < KSPL; k4 += 4) {
            float4 wa = *(const float4*)(wrA + k4);
            float4 wb = *(const float4*)(wrB + k4);
            #pragma unroll
            for (int kk = 0; kk < 4; ++kk) {
                const float* arow = aB + (k4 + kk) * 32;
                ulonglong2 a01 = *(const ulonglong2*)(arow);
                ulonglong2 a23 = *(const ulonglong2*)(arow + 4);
                float wak = (kk == 0) ? wa.x : (kk == 1) ? wa.y
                          : (kk == 2) ? wa.z : wa.w;
                float wbk = (kk == 0) ? wb.x : (kk == 1) ? wb.y
                          : (kk == 2) ? wb.z : wb.w;
                unsigned long long wa2 = pack2(wak);
                unsigned long long wb2 = pack2(wbk);
                ffma2(acc[0][0], a01.x, wa2); ffma2(acc[0][1], a01.x, wb2);
                ffma2(acc[1][0], a01.y, wa2); ffma2(acc[1][1], a01.y, wb2);
                ffma2(acc[2][0], a23.x, wa2); ffma2(acc[2][1], a23.x, wb2);
                ffma2(acc[3][0], a23.y, wa2); ffma2(acc[3][1], a23.y, wb2);
            }
        }

        // ---- split-K reduce: kh1 -> smem; kh0 adds ----
        if (kh == 1) {
            unsigned long long* d0 = sRed + (size_t)slot * RED_PITCH;
            #pragma unroll
            for (int p = 0; p < 4; ++p)
                *(ulonglong2*)(d0 + 2 * p) = make_ulonglong2(acc[p][0], acc[p][1]);
        }
        __syncthreads();

        if (kh == 0) {
            const unsigned long long* s0 = sRed + (size_t)slot * RED_PITCH;
            #pragma unroll
            for (int p = 0; p < 4; ++p) {
                ulonglong2 v = *(const ulonglong2*)(s0 + 2 * p);
                fadd2(acc[p][0], v.x); fadd2(acc[p][1], v.y);
            }

            // ---- epilogue: lanes<16 (i,g); lanes>=16 (f,o) ----
            float zA[8], zB[8];
            #pragma unroll
            for (int p = 0; p < 4; ++p) {
                unpack2(acc[p][0], zA[2 * p], zA[2 * p + 1]);
                unpack2(acc[p][1], zB[2 * p], zB[2 * p + 1]);
            }
            float v[8];
            if (lane < 16) {
                #pragma unroll
                for (int r = 0; r < 8; ++r)
                    v[r] = fsig(zA[r] + biasA) * ftanh_(zB[r] + biasB);
            }
            #pragma unroll
            for (int r = 0; r < 8; ++r)
                v[r] = __shfl_sync(0xffffffffu, v[r], lane ^ 16);
            if (lane >= 16) {
                float h[8];
                #pragma unroll
                for (int r = 0; r < 8; ++r) {
                    float cn = fsig(zA[r] + biasA) * c_reg[r] + v[r];
                    c_reg[r] = cn;
                    h[r] = fsig(zB[r] + biasB) * ftanh_(cn);
                    out[(size_t)(m0 + wm * 8 + r) * ((size_t)T_ * H_) +
                        (size_t)t * H_ + j] = h[r];
                }
                float* hdst = &g_hT[t & 1][mb][j][wm * 8];
                *(float4*)(hdst)     = make_float4(h[0], h[1], h[2], h[3]);
                *(float4*)(hdst + 4) = make_float4(h[4], h[5], h[6], h[7]);
            }
            bar_named(3);                             // warps 0-3 only
            if (tid == 0) {
                __threadfence();
                st_rel(&g_flags[mb][ub], (unsigned)(t + 1));
            }
        } else if (t + 1 < T_) {
            // ---- kh1 warps: prefetch x(t+1) during kh0's epilogue ----
            int lt = tid - 128;
            int d = lt & 31, mg = lt >> 5;            // coalesced LDG
            #pragma unroll
            for (int rr = 0; rr < 8; ++rr) {
                int m = mg * 8 + rr;
                sAT[(512 + d) * 32 + m] =
                    x[(size_t)(m0 + m) * (T_ * D_) + (size_t)(t + 1) * D_ + d];
            }
            bar_named(2);                             // order STS vs next k-loop
        }
        // no trailing syncthreads: step-top poll + syncthreads rejoins halves
    }
}

extern "C" void kernel_launch(void* const* d_in, const int* in_sizes, int n_in,
                              void* d_out, int out_size) {
    const float* x  = (const float*)d_in[0];
    const float* Wx = (const float*)d_in[1];
    const float* Wh = (const float*)d_in[2];
    const float* b  = (const float*)d_in[3];
    float* out = (float*)d_out;

    static bool attr_set = false;
    if (!attr_set) {
        cudaFuncSetAttribute(lstm_persistent,
                             cudaFuncAttributeMaxDynamicSharedMemorySize,
                             SMEM_BYTES);
        attr_set = true;
    }

    init_flags_kernel<<<1, 128>>>();
    lstm_persistent<<<NCTA, NTHR, SMEM_BYTES>>>(x, Wx, Wh, b, out);
}

// round 11
// speedup vs baseline: 1.2704x; 1.2130x over previous
#include <cuda_runtime.h>

// Persistent LSTM: B=128, T=365, D=32, H=512, fp32, out[b,t,:]=h_t.
// R6 skeleton: 128 CTAs x 256 threads (8 warps), CTA tile 32 batch x 16
// units, split-K halves (kh0/kh1), W transposed resident in smem, A
// transposed sAT[k][m], packed fma.rn.f32x2, gate pairs (i,f),(g,o).
// R11: two-phase dataflow step. Producers ub0-15 arrive on cnt[mb][0],
// ub16-31 on cnt[mb][1]. Consumer: poll cnt0 -> stage h[0,256) -> compute
// k[0,256) -> poll cnt1 (hidden by phase-0 compute) -> stage h[256,512)+x ->
// compute k[256,544). x pre-transposed once to g_xT[mb][t][d][m] (4KB/step
// contiguous cp.async). One reduce sync. RED_PITCH=10 (16B-aligned).

#define B_   128
#define T_   365
#define D_   32
#define H_   512
#define G4   2048
#define KTOT 544
#define NCTA 128
#define NTHR 256
#define WPITCH 548

#define SW_FLOATS (64 * WPITCH)            // 35072
#define SA_OFF    SW_FLOATS
#define SA_FLOATS (KTOT * 32)              // 17408
#define RED_OFF   (SA_OFF + SA_FLOATS)     // 52480
#define RED_PITCH 10                       // u64/slot; 80B -> 16B aligned
#define SMEM_BYTES (RED_OFF * 4 + 128 * RED_PITCH * 8)   // 220160

__device__ float g_hT[2][4][512][32];      // [parity][mb][unit][m-local]
__device__ float g_xT[4][T_][32][32];      // [mb][t][d][m-local] (~6MB)
__device__ unsigned int g_cnt[4][2];       // per-(mb, producer-half) arrivals
__device__ unsigned int g_init[4];         // prologue x-transpose barrier

__global__ void init_ctrl_kernel() {
    if (threadIdx.x < 8)  ((unsigned int*)g_cnt)[threadIdx.x] = 0u;
    if (threadIdx.x < 4)  g_init[threadIdx.x] = 0u;
}

__device__ __forceinline__ unsigned long long pack2(float v) {
    unsigned long long r;
    asm("mov.b64 %0, {%1, %1};" : "=l"(r) : "f"(v));
    return r;
}
__device__ __forceinline__ void ffma2(unsigned long long& d,
                                      unsigned long long a,
                                      unsigned long long b) {
    asm("fma.rn.f32x2 %0, %1, %2, %0;" : "+l"(d) : "l"(a), "l"(b));
}
__device__ __forceinline__ void fadd2(unsigned long long& d, unsigned long long a) {
    asm("add.rn.f32x2 %0, %0, %1;" : "+l"(d) : "l"(a));
}
__device__ __forceinline__ void unpack2(unsigned long long v, float& lo, float& hi) {
    asm("mov.b64 {%0, %1}, %2;" : "=f"(lo), "=f"(hi) : "l"(v));
}
__device__ __forceinline__ float fsig(float z) {
    return 1.0f / (1.0f + __expf(-z));
}
__device__ __forceinline__ float ftanh_(float z) {
    return 1.0f - 2.0f / (__expf(2.0f * z) + 1.0f);
}
__device__ __forceinline__ void cp_async16(unsigned int smem_dst, const void* gsrc) {
    asm volatile("cp.async.cg.shared.global [%0], [%1], 16;"
                 :: "r"(smem_dst), "l"(gsrc) : "memory");
}
__device__ __forceinline__ void cp_async_wait_all() {
    asm volatile("cp.async.commit_group;\n\tcp.async.wait_group 0;" ::: "memory");
}
__device__ __forceinline__ unsigned int smem_u32(const void* p) {
    return (unsigned int)__cvta_generic_to_shared(p);
}
__device__ __forceinline__ unsigned int ld_acq(const unsigned int* p) {
    unsigned int v;
    asm volatile("ld.acquire.gpu.global.u32 %0, [%1];" : "=r"(v) : "l"(p));
    return v;
}
__device__ __forceinline__ void bar_named(int id) {
    asm volatile("bar.sync %0, 128;" :: "r"(id) : "memory");
}

// k-chunk macro: per lane 8 m x 2 gate-col rows, f32x2 over m-pairs.
#define KCHUNK(koff, klen)                                                    \
    _Pragma("unroll 2")                                                       \
    for (int k4 = 0; k4 < (klen); k4 += 4) {                                  \
        float4 wa = *(const float4*)(wrA + (koff) + k4);                      \
        float4 wb = *(const float4*)(wrB + (koff) + k4);                      \
        _Pragma("unroll")                                                     \
        for (int kk = 0; kk < 4; ++kk) {                                      \
            const float* arow = sAT + ((koff) + k4 + kk) * 32 + wm * 8;       \
            ulonglong2 a01 = *(const ulonglong2*)(arow);                      \
            ulonglong2 a23 = *(const ulonglong2*)(arow + 4);                  \
            float wak = (kk == 0) ? wa.x : (kk == 1) ? wa.y                   \
                      : (kk == 2) ? wa.z : wa.w;                              \
            float wbk = (kk == 0) ? wb.x : (kk == 1) ? wb.y                   \
                      : (kk == 2) ? wb.z : wb.w;                              \
            unsigned long long wa2 = pack2(wak);                              \
            unsigned long long wb2 = pack2(wbk);                              \
            ffma2(acc[0][0], a01.x, wa2); ffma2(acc[0][1], a01.x, wb2);       \
            ffma2(acc[1][0], a01.y, wa2); ffma2(acc[1][1], a01.y, wb2);       \
            ffma2(acc[2][0], a23.x, wa2); ffma2(acc[2][1], a23.x, wb2);       \
            ffma2(acc[3][0], a23.y, wa2); ffma2(acc[3][1], a23.y, wb2);       \
        }                                                                     \
    }

__global__ __launch_bounds__(NTHR, 1) void lstm_persistent(
    const float* __restrict__ x,    // [B,T,D]
    const float* __restrict__ Wx,   // [D,4H]
    const float* __restrict__ Wh,   // [H,4H]
    const float* __restrict__ bias, // [4H]
    float* __restrict__ out)        // [B,T,H]
{
    extern __shared__ float smem[];
    float* sWT = smem;                                // [64][WPITCH]
    float* sAT = smem + SA_OFF;                       // [544][32]
    unsigned long long* sRed = (unsigned long long*)(smem + RED_OFF);
    float* sX = (float*)sRed;                         // prologue scratch [32][33]
    const unsigned int sATb = smem_u32(sAT);

    const int tid  = threadIdx.x;
    const int warp = tid >> 5;
    const int lane = tid & 31;
    const int wm   = warp & 3;                 // m-subtile (rows 8wm..8wm+7)
    const int kh   = warp >> 2;                // k-half 0/1
    const int ub   = blockIdx.x & 31;
    const int mb   = blockIdx.x >> 5;
    const int j0   = ub * 16;
    const int m0   = mb * 32;
    const int u    = lane & 15;
    const int gA   = lane >> 4;
    const int j    = j0 + u;

    // ---- prologue: W transposed; zero h rows of sAT ----
    for (int i = 0; i < (64 * KTOT) / NTHR; ++i) {    // 136 iters
        int idx = i * NTHR + tid;
        int r = idx & 63;
        int k = idx >> 6;
        int col = (r >> 4) * H_ + j0 + (r & 15);
        float v = (k < H_) ? Wh[(size_t)k * G4 + col]
                           : Wx[(size_t)(k - H_) * G4 + col];
        sWT[r * WPITCH + k] = v;
    }
    {
        float4 z4 = make_float4(0.f, 0.f, 0.f, 0.f);
        #pragma unroll
        for (int i = 0; i < 16; ++i)                  // rows [0,512)
            *(float4*)(sAT + (i * NTHR + tid) * 4) = z4;
    }

    // ---- prologue: transpose this CTA's share of x into g_xT ----
    for (int tt = ub; tt < T_; tt += 32) {
        float v[4];
        #pragma unroll
        for (int i = 0; i < 4; ++i) {                 // coalesced LDG (lane->d)
            int e = i * NTHR + tid;
            int m = e >> 5, d = e & 31;
            v[i] = x[(size_t)(m0 + m) * (T_ * D_) + (size_t)tt * D_ + d];
        }
        __syncthreads();
        #pragma unroll
        for (int i = 0; i < 4; ++i) {                 // conflict-free STS (pad 33)
            int e = i * NTHR + tid;
            int m = e >> 5, d = e & 31;
            sX[d * 33 + m] = v[i];
        }
        __syncthreads();
        #pragma unroll
        for (int i = 0; i < 4; ++i) {                 // coalesced STG (lane->m)
            int e = i * NTHR + tid;
            int d = e >> 5, m = e & 31;
            g_xT[mb][tt][d][m] = sX[d * 33 + m];
        }
    }
    __threadfence();
    __syncthreads();
    if (tid == 0) {
        atomicAdd(&g_init[mb], 1u);
        while (ld_acq(&g_init[mb]) < 32u) { }
    }
    __syncthreads();

    // stage x(0) (contiguous from g_xT)
    cp_async16(sATb + (unsigned)(4096 + tid) * 16, &g_xT[mb][0][0][0] + tid * 4);
    cp_async_wait_all();

    const float biasA = bias[gA * H_ + j];
    const float biasB = bias[(gA + 2) * H_ + j];
    float c_reg[8] = {0.f,0.f,0.f,0.f,0.f,0.f,0.f,0.f};
    __syncthreads();

    const float* wrA = sWT + lane * WPITCH;
    const float* wrB = wrA + 32 * WPITCH;
    const int slot = wm * 32 + lane;
    const int kOff0 = kh * 128;          // phase-0 range start
    const int kOff1 = 256 + kh * 128;    // phase-1 range start
    const int kOffX = 512 + kh * 16;     // x range start

    for (int t = 0; t < T_; ++t) {
        unsigned long long acc[4][2] = {};

        // ---- phase 0: producers ub 0-15 (units 0-255) ----
        if (t > 0) {
            if (tid == 0) {
                unsigned tgt = 16u * (unsigned)t;
                while (ld_acq(&g_cnt[mb][0]) < tgt) { }
            }
            __syncthreads();
            const float* hsrc = &g_hT[(t - 1) & 1][mb][0][0];
            #pragma unroll
            for (int i = 0; i < 8; ++i) {            // 2048 f4 = rows [0,256)
                int f4 = i * NTHR + tid;
                cp_async16(sATb + (unsigned)f4 * 16, hsrc + (size_t)f4 * 4);
            }
            cp_async_wait_all();
            __syncthreads();
        }
        KCHUNK(kOff0, 128)

        // ---- phase 1: producers ub 16-31 (units 256-511) + x(t) ----
        if (t > 0) {
            if (tid == 0) {
                unsigned tgt = 16u * (unsigned)t;
                while (ld_acq(&g_cnt[mb][1]) < tgt) { }
            }
            __syncthreads();
            const float* hsrc = &g_hT[(t - 1) & 1][mb][0][0];
            #pragma unroll
            for (int i = 0; i < 8; ++i) {            // rows [256,512)
                int f4 = 2048 + i * NTHR + tid;
                cp_async16(sATb + (unsigned)f4 * 16, hsrc + (size_t)f4 * 4);
            }
            // x(t): 4KB contiguous
            cp_async16(sATb + (unsigned)(4096 + tid) * 16,
                       &g_xT[mb][t][0][0] + tid * 4);
            cp_async_wait_all();
            __syncthreads();
        }
        KCHUNK(kOff1, 128)
        KCHUNK(kOffX, 16)

        // ---- split-K reduce (one sync; reuse ordered by next phase-0 sync) ----
        if (kh == 1) {
            unsigned long long* d0 = sRed + (size_t)slot * RED_PITCH;
            #pragma unroll
            for (int p = 0; p < 4; ++p)
                *(ulonglong2*)(d0 + 2 * p) = make_ulonglong2(acc[p][0], acc[p][1]);
        }
        __syncthreads();

        if (kh == 0) {
            const unsigned long long* s0 = sRed + (size_t)slot * RED_PITCH;
            #pragma unroll
            for (int p = 0; p < 4; ++p) {
                ulonglong2 v = *(const ulonglong2*)(s0 + 2 * p);
                fadd2(acc[p][0], v.x); fadd2(acc[p][1], v.y);
            }

            // ---- epilogue: lanes<16 (i,g); lanes>=16 (f,o) ----
            float zA[8], zB[8];
            #pragma unroll
            for (int p = 0; p < 4; ++p) {
                unpack2(acc[p][0], zA[2 * p], zA[2 * p + 1]);
                unpack2(acc[p][1], zB[2 * p], zB[2 * p + 1]);
            }
            float v[8];
            if (lane < 16) {
                #pragma unroll
                for (int r = 0; r < 8; ++r)
                    v[r] = fsig(zA[r] + biasA) * ftanh_(zB[r] + biasB);
            }
            #pragma unroll
            for (int r = 0; r < 8; ++r)
                v[r] = __shfl_sync(0xffffffffu, v[r], lane ^ 16);
            if (lane >= 16) {
                float h[8];
                #pragma unroll
                for (int r = 0; r < 8; ++r) {
                    float cn = fsig(zA[r] + biasA) * c_reg[r] + v[r];
                    c_reg[r] = cn;
                    h[r] = fsig(zB[r] + biasB) * ftanh_(cn);
                    out[(size_t)(m0 + wm * 8 + r) * ((size_t)T_ * H_) +
                        (size_t)t * H_ + j] = h[r];
                }
                float* hdst = &g_hT[t & 1][mb][j][wm * 8];
                *(float4*)(hdst)     = make_float4(h[0], h[1], h[2], h[3]);
                *(float4*)(hdst + 4) = make_float4(h[4], h[5], h[6], h[7]);
            }
            bar_named(3);                             // warps 0-3
            if (tid == 0) {
                __threadfence();
                atomicAdd(&g_cnt[mb][ub >> 4], 1u);   // arrive on my half
            }
        }
    }
}

extern "C" void kernel_launch(void* const* d_in, const int* in_sizes, int n_in,
                              void* d_out, int out_size) {
    const float* x  = (const float*)d_in[0];
    const float* Wx = (const float*)d_in[1];
    const float* Wh = (const float*)d_in[2];
    const float* b  = (const float*)d_in[3];
    float* out = (float*)d_out;

    static bool attr_set = false;
    if (!attr_set) {
        cudaFuncSetAttribute(lstm_persistent,
                             cudaFuncAttributeMaxDynamicSharedMemorySize,
                             SMEM_BYTES);
        attr_set = true;
    }

    init_ctrl_kernel<<<1, 32>>>();
    lstm_persistent<<<NCTA, NTHR, SMEM_BYTES>>>(x, Wx, Wh, b, out);
}

// round 12
// speedup vs baseline: 1.3262x; 1.0439x over previous
#include <cuda_runtime.h>

// Persistent LSTM: B=128, T=365, D=32, H=512, fp32, out[b,t,:]=h_t.
// R11 skeleton: 128 CTAs x 256 threads, CTA tile 32 batch x 16 units,
// split-K halves, W transposed resident, A transposed sAT[k][m], f32x2 FFMA,
// two-phase producer counters cnt[mb][0|1], x pre-transposed to g_xT.
// R12: pipelined staging. Issue cp.async group A (h[0,256)) and group B
// (h[256,512)) up front after their polls; compute x-chunk (h-independent)
// to cover A's flight; wait_group 1 -> compute k[0,256); wait_group 0 ->
// compute k[256,512). x(t+1) staged by kh1 warps during kh0's epilogue.

#define B_   128
#define T_   365
#define D_   32
#define H_   512
#define G4   2048
#define KTOT 544
#define NCTA 128
#define NTHR 256
#define WPITCH 548

#define SW_FLOATS (64 * WPITCH)            // 35072
#define SA_OFF    SW_FLOATS
#define SA_FLOATS (KTOT * 32)              // 17408
#define RED_OFF   (SA_OFF + SA_FLOATS)     // 52480
#define RED_PITCH 10                       // u64/slot; 80B -> 16B aligned
#define SMEM_BYTES (RED_OFF * 4 + 128 * RED_PITCH * 8)   // 220160

__device__ float g_hT[2][4][512][32];      // [parity][mb][unit][m-local]
__device__ float g_xT[4][T_][32][32];      // [mb][t][d][m-local]
__device__ unsigned int g_cnt[4][2];       // per-(mb, producer-half) arrivals
__device__ unsigned int g_init[4];         // prologue x-transpose barrier

__global__ void init_ctrl_kernel() {
    if (threadIdx.x < 8)  ((unsigned int*)g_cnt)[threadIdx.x] = 0u;
    if (threadIdx.x < 4)  g_init[threadIdx.x] = 0u;
}

__device__ __forceinline__ unsigned long long pack2(float v) {
    unsigned long long r;
    asm("mov.b64 %0, {%1, %1};" : "=l"(r) : "f"(v));
    return r;
}
__device__ __forceinline__ void ffma2(unsigned long long& d,
                                      unsigned long long a,
                                      unsigned long long b) {
    asm("fma.rn.f32x2 %0, %1, %2, %0;" : "+l"(d) : "l"(a), "l"(b));
}
__device__ __forceinline__ void fadd2(unsigned long long& d, unsigned long long a) {
    asm("add.rn.f32x2 %0, %0, %1;" : "+l"(d) : "l"(a));
}
__device__ __forceinline__ void unpack2(unsigned long long v, float& lo, float& hi) {
    asm("mov.b64 {%0, %1}, %2;" : "=f"(lo), "=f"(hi) : "l"(v));
}
__device__ __forceinline__ float fsig(float z) {
    return 1.0f / (1.0f + __expf(-z));
}
__device__ __forceinline__ float ftanh_(float z) {
    return 1.0f - 2.0f / (__expf(2.0f * z) + 1.0f);
}
__device__ __forceinline__ void cp_async16(unsigned int smem_dst, const void* gsrc) {
    asm volatile("cp.async.cg.shared.global [%0], [%1], 16;"
                 :: "r"(smem_dst), "l"(gsrc) : "memory");
}
#define CP_COMMIT() asm volatile("cp.async.commit_group;" ::: "memory")
#define CP_WAIT(N)  asm volatile("cp.async.wait_group %0;" :: "n"(N) : "memory")
__device__ __forceinline__ unsigned int smem_u32(const void* p) {
    return (unsigned int)__cvta_generic_to_shared(p);
}
__device__ __forceinline__ unsigned int ld_acq(const unsigned int* p) {
    unsigned int v;
    asm volatile("ld.acquire.gpu.global.u32 %0, [%1];" : "=r"(v) : "l"(p));
    return v;
}
__device__ __forceinline__ void bar_named(int id) {
    asm volatile("bar.sync %0, 128;" :: "r"(id) : "memory");
}

// k-chunk: per lane 8 m x 2 gate-col rows, f32x2 over m-pairs.
#define KCHUNK(koff, klen)                                                    \
    _Pragma("unroll 2")                                                       \
    for (int k4 = 0; k4 < (klen); k4 += 4) {                                  \
        float4 wa = *(const float4*)(wrA + (koff) + k4);                      \
        float4 wb = *(const float4*)(wrB + (koff) + k4);                      \
        _Pragma("unroll")                                                     \
        for (int kk = 0; kk < 4; ++kk) {                                      \
            const float* arow = sAT + ((koff) + k4 + kk) * 32 + wm * 8;       \
            ulonglong2 a01 = *(const ulonglong2*)(arow);                      \
            ulonglong2 a23 = *(const ulonglong2*)(arow + 4);                  \
            float wak = (kk == 0) ? wa.x : (kk == 1) ? wa.y                   \
                      : (kk == 2) ? wa.z : wa.w;                              \
            float wbk = (kk == 0) ? wb.x : (kk == 1) ? wb.y                   \
                      : (kk == 2) ? wb.z : wb.w;                              \
            unsigned long long wa2 = pack2(wak);                              \
            unsigned long long wb2 = pack2(wbk);                              \
            ffma2(acc[0][0], a01.x, wa2); ffma2(acc[0][1], a01.x, wb2);       \
            ffma2(acc[1][0], a01.y, wa2); ffma2(acc[1][1], a01.y, wb2);       \
            ffma2(acc[2][0], a23.x, wa2); ffma2(acc[2][1], a23.x, wb2);       \
            ffma2(acc[3][0], a23.y, wa2); ffma2(acc[3][1], a23.y, wb2);       \
        }                                                                     \
    }

__global__ __launch_bounds__(NTHR, 1) void lstm_persistent(
    const float* __restrict__ x,    // [B,T,D]
    const float* __restrict__ Wx,   // [D,4H]
    const float* __restrict__ Wh,   // [H,4H]
    const float* __restrict__ bias, // [4H]
    float* __restrict__ out)        // [B,T,H]
{
    extern __shared__ float smem[];
    float* sWT = smem;                                // [64][WPITCH]
    float* sAT = smem + SA_OFF;                       // [544][32]
    unsigned long long* sRed = (unsigned long long*)(smem + RED_OFF);
    float* sX = (float*)sRed;                         // prologue scratch [32][33]
    const unsigned int sATb = smem_u32(sAT);

    const int tid  = threadIdx.x;
    const int warp = tid >> 5;
    const int lane = tid & 31;
    const int wm   = warp & 3;                 // m-subtile (rows 8wm..8wm+7)
    const int kh   = warp >> 2;                // k-half 0/1
    const int ub   = blockIdx.x & 31;
    const int mb   = blockIdx.x >> 5;
    const int j0   = ub * 16;
    const int m0   = mb * 32;
    const int u    = lane & 15;
    const int gA   = lane >> 4;
    const int j    = j0 + u;

    // ---- prologue: W transposed; zero h rows of sAT ----
    for (int i = 0; i < (64 * KTOT) / NTHR; ++i) {    // 136 iters
        int idx = i * NTHR + tid;
        int r = idx & 63;
        int k = idx >> 6;
        int col = (r >> 4) * H_ + j0 + (r & 15);
        float v = (k < H_) ? Wh[(size_t)k * G4 + col]
                           : Wx[(size_t)(k - H_) * G4 + col];
        sWT[r * WPITCH + k] = v;
    }
    {
        float4 z4 = make_float4(0.f, 0.f, 0.f, 0.f);
        #pragma unroll
        for (int i = 0; i < 16; ++i)                  // rows [0,512)
            *(float4*)(sAT + (i * NTHR + tid) * 4) = z4;
    }

    // ---- prologue: transpose this CTA's share of x into g_xT ----
    for (int tt = ub; tt < T_; tt += 32) {
        float v[4];
        #pragma unroll
        for (int i = 0; i < 4; ++i) {
            int e = i * NTHR + tid;
            int m = e >> 5, d = e & 31;
            v[i] = x[(size_t)(m0 + m) * (T_ * D_) + (size_t)tt * D_ + d];
        }
        __syncthreads();
        #pragma unroll
        for (int i = 0; i < 4; ++i) {
            int e = i * NTHR + tid;
            int m = e >> 5, d = e & 31;
            sX[d * 33 + m] = v[i];
        }
        __syncthreads();
        #pragma unroll
        for (int i = 0; i < 4; ++i) {
            int e = i * NTHR + tid;
            int d = e >> 5, m = e & 31;
            g_xT[mb][tt][d][m] = sX[d * 33 + m];
        }
    }
    __threadfence();
    __syncthreads();
    if (tid == 0) {
        atomicAdd(&g_init[mb], 1u);
        while (ld_acq(&g_init[mb]) < 32u) { }
    }
    __syncthreads();

    // stage x(0)
    cp_async16(sATb + (unsigned)(4096 + tid) * 16, &g_xT[mb][0][0][0] + tid * 4);
    CP_COMMIT(); CP_WAIT(0);

    const float biasA = bias[gA * H_ + j];
    const float biasB = bias[(gA + 2) * H_ + j];
    float c_reg[8] = {0.f,0.f,0.f,0.f,0.f,0.f,0.f,0.f};
    __syncthreads();

    const float* wrA = sWT + lane * WPITCH;
    const float* wrB = wrA + 32 * WPITCH;
    const int slot = wm * 32 + lane;
    const int kOff0 = kh * 128;
    const int kOff1 = 256 + kh * 128;
    const int kOffX = 512 + kh * 16;

    for (int t = 0; t < T_; ++t) {
        unsigned long long acc[4][2] = {};

        // ---- issue both h-phase copies up front ----
        if (t > 0) {
            const float* hsrc = &g_hT[(t - 1) & 1][mb][0][0];
            if (tid == 0) {
                unsigned tgt = 16u * (unsigned)t;
                while (ld_acq(&g_cnt[mb][0]) < tgt) { }
            }
            __syncthreads();
            #pragma unroll
            for (int i = 0; i < 8; ++i) {             // group A: rows [0,256)
                int f4 = i * NTHR + tid;
                cp_async16(sATb + (unsigned)f4 * 16, hsrc + (size_t)f4 * 4);
            }
            CP_COMMIT();
            if (tid == 0) {
                unsigned tgt = 16u * (unsigned)t;
                while (ld_acq(&g_cnt[mb][1]) < tgt) { }
            }
            __syncthreads();
            #pragma unroll
            for (int i = 0; i < 8; ++i) {             // group B: rows [256,512)
                int f4 = 2048 + i * NTHR + tid;
                cp_async16(sATb + (unsigned)f4 * 16, hsrc + (size_t)f4 * 4);
            }
            CP_COMMIT();
        }

        // ---- x-chunk first: h-independent, covers group A's flight ----
        KCHUNK(kOffX, 16)

        if (t > 0) { CP_WAIT(1); }                    // A complete
        __syncthreads();
        KCHUNK(kOff0, 128)

        if (t > 0) { CP_WAIT(0); }                    // B complete
        __syncthreads();
        KCHUNK(kOff1, 128)

        // ---- split-K reduce ----
        if (kh == 1) {
            unsigned long long* d0 = sRed + (size_t)slot * RED_PITCH;
            #pragma unroll
            for (int p = 0; p < 4; ++p)
                *(ulonglong2*)(d0 + 2 * p) = make_ulonglong2(acc[p][0], acc[p][1]);
        }
        __syncthreads();

        if (kh == 0) {
            const unsigned long long* s0 = sRed + (size_t)slot * RED_PITCH;
            #pragma unroll
            for (int p = 0; p < 4; ++p) {
                ulonglong2 v = *(const ulonglong2*)(s0 + 2 * p);
                fadd2(acc[p][0], v.x); fadd2(acc[p][1], v.y);
            }

            // ---- epilogue: lanes<16 (i,g); lanes>=16 (f,o) ----
            float zA[8], zB[8];
            #pragma unroll
            for (int p = 0; p < 4; ++p) {
                unpack2(acc[p][0], zA[2 * p], zA[2 * p + 1]);
                unpack2(acc[p][1], zB[2 * p], zB[2 * p + 1]);
            }
            float v[8];
            if (lane < 16) {
                #pragma unroll
                for (int r = 0; r < 8; ++r)
                    v[r] = fsig(zA[r] + biasA) * ftanh_(zB[r] + biasB);
            }
            #pragma unroll
            for (int r = 0; r < 8; ++r)
                v[r] = __shfl_sync(0xffffffffu, v[r], lane ^ 16);
            if (lane >= 16) {
                float h[8];
                #pragma unroll
                for (int r = 0; r < 8; ++r) {
                    float cn = fsig(zA[r] + biasA) * c_reg[r] + v[r];
                    c_reg[r] = cn;
                    h[r] = fsig(zB[r] + biasB) * ftanh_(cn);
                    out[(size_t)(m0 + wm * 8 + r) * ((size_t)T_ * H_) +
                        (size_t)t * H_ + j] = h[r];
                }
                float* hdst = &g_hT[t & 1][mb][j][wm * 8];
                *(float4*)(hdst)     = make_float4(h[0], h[1], h[2], h[3]);
                *(float4*)(hdst + 4) = make_float4(h[4], h[5], h[6], h[7]);
            }
            bar_named(3);                             // warps 0-3
            if (tid == 0) {
                __threadfence();
                atomicAdd(&g_cnt[mb][ub >> 4], 1u);
            }
        } else if (t + 1 < T_) {
            // ---- kh1 warps: stage x(t+1) during kh0's epilogue ----
            const float* xsrc = &g_xT[mb][t + 1][0][0];
            int lt = tid - 128;
            #pragma unroll
            for (int i = 0; i < 2; ++i) {
                int f4 = 4096 + i * 128 + lt;
                cp_async16(sATb + (unsigned)f4 * 16,
                           xsrc + (size_t)(i * 128 + lt) * 4);
            }
            CP_COMMIT(); CP_WAIT(0);
            // visibility to kh0 warps: ordered by next step's poll syncthreads
        }
    }
}

extern "C" void kernel_launch(void* const* d_in, const int* in_sizes, int n_in,
                              void* d_out, int out_size) {
    const float* x  = (const float*)d_in[0];
    const float* Wx = (const float*)d_in[1];
    const float* Wh = (const float*)d_in[2];
    const float* b  = (const float*)d_in[3];
    float* out = (float*)d_out;

    static bool attr_set = false;
    if (!attr_set) {
        cudaFuncSetAttribute(lstm_persistent,
                             cudaFuncAttributeMaxDynamicSharedMemorySize,
                             SMEM_BYTES);
        attr_set = true;
    }

    init_ctrl_kernel<<<1, 32>>>();
    lstm_persistent<<<NCTA, NTHR, SMEM_BYTES>>>(x, Wx, Wh, b, out);
}

// round 13
// speedup vs baseline: 2.4337x; 1.8351x over previous
#include <cuda_runtime.h>
#include <cuda_bf16.h>
#include <cstdint>

// Persistent LSTM: B=128, T=365, D=32, H=512, fp32 I/O, out[b,t,:]=h_t.
// 128 CTAs x 256 threads. CTA tile 32 batch(m) x 16 units x 4 gates (n=64,
// n = u_local*4 + gate). GEMM on tensor pipe: mma.sync m16n8k16 bf16, fp32
// accum, 3-MMA split (hi*hi + hi*lo + lo*hi) for ~fp32 precision.
// W resident in smem as [n][k] bf16 hi/lo planes (pitch 1104B). A (h|x) in
// smem [k][hi m0-31 | lo m0-31] rows (pitch 144B), staged per step via
// cp.async from g_h (producers write h as bf16 hi/lo) and g_x (prologue-
// transposed x). R12 exchange skeleton: two producer-half counters,
// pipelined commit groups X/A/B. No split-K -> no reduce phase.

#define B_   128
#define T_   365
#define D_   32
#define H_   512
#define G4   2048
#define KTOT 544
#define NCTA 128
#define NTHR 256

#define SWP   1104                    // W row pitch bytes (552 bf16)
#define SWLO  (64 * SWP)              // lo-plane offset = 70656
#define SW_BYTES (128 * SWP)          // 141312
#define SAP   144                     // A row pitch bytes ([hi 64B | lo 64B] + pad)
#define SA_BYTES (KTOT * SAP)         // 78336
#define SMEM_BYTES (SW_BYTES + SA_BYTES)   // 219648

__device__ unsigned char g_h[2][4][512][128];   // [parity][mb][unit][hi32|lo32 bf16]
__device__ unsigned char g_x[4][T_][32][128];   // [mb][t][d][hi32|lo32 bf16]
__device__ unsigned int g_cnt[4][2];
__device__ unsigned int g_init[4];

__global__ void init_ctrl_kernel() {
    if (threadIdx.x < 8) ((unsigned int*)g_cnt)[threadIdx.x] = 0u;
    if (threadIdx.x < 4) g_init[threadIdx.x] = 0u;
}

__device__ __forceinline__ float fsig(float z) {
    return 1.0f / (1.0f + __expf(-z));
}
__device__ __forceinline__ float ftanh_(float z) {
    return 1.0f - 2.0f / (__expf(2.0f * z) + 1.0f);
}
__device__ __forceinline__ void cp_async16(unsigned int smem_dst, const void* gsrc) {
    asm volatile("cp.async.cg.shared.global [%0], [%1], 16;"
                 :: "r"(smem_dst), "l"(gsrc) : "memory");
}
#define CP_COMMIT() asm volatile("cp.async.commit_group;" ::: "memory")
#define CP_WAIT(N)  asm volatile("cp.async.wait_group %0;" :: "n"(N) : "memory")
__device__ __forceinline__ unsigned int smem_u32(const void* p) {
    return (unsigned int)__cvta_generic_to_shared(p);
}
__device__ __forceinline__ unsigned int ld_acq(const unsigned int* p) {
    unsigned int v;
    asm volatile("ld.acquire.gpu.global.u32 %0, [%1];" : "=r"(v) : "l"(p));
    return v;
}
__device__ __forceinline__ void ldsm4(uint32_t& r0, uint32_t& r1, uint32_t& r2,
                                      uint32_t& r3, uint32_t a) {
    asm volatile("ldmatrix.sync.aligned.m8n8.x4.shared.b16 {%0,%1,%2,%3}, [%4];"
                 : "=r"(r0), "=r"(r1), "=r"(r2), "=r"(r3) : "r"(a));
}
__device__ __forceinline__ void ldsm4t(uint32_t& r0, uint32_t& r1, uint32_t& r2,
                                       uint32_t& r3, uint32_t a) {
    asm volatile("ldmatrix.sync.aligned.m8n8.x4.trans.shared.b16 {%0,%1,%2,%3}, [%4];"
                 : "=r"(r0), "=r"(r1), "=r"(r2), "=r"(r3) : "r"(a));
}
__device__ __forceinline__ void mma16816(float* c,
                                         uint32_t a0, uint32_t a1, uint32_t a2,
                                         uint32_t a3, uint32_t b0, uint32_t b1) {
    asm volatile(
        "mma.sync.aligned.m16n8k16.row.col.f32.bf16.bf16.f32 "
        "{%0,%1,%2,%3}, {%4,%5,%6,%7}, {%8,%9}, {%0,%1,%2,%3};"
        : "+f"(c[0]), "+f"(c[1]), "+f"(c[2]), "+f"(c[3])
        : "r"(a0), "r"(a1), "r"(a2), "r"(a3), "r"(b0), "r"(b1));
}
__device__ __forceinline__ void store_h_bf(unsigned char* row, int mloc, float h) {
    __nv_bfloat16 hi = __float2bfloat16(h);
    float lo = h - __bfloat162float(hi);
    *(__nv_bfloat16*)(row + mloc * 2) = hi;
    *(__nv_bfloat16*)(row + 64 + mloc * 2) = __float2bfloat16(lo);
}

// One k16 iteration: 4 ldmatrix + 6 mma (hi*hi, hi*lo, lo*hi).
#define MMAIT(K0) do {                                                        \
    uint32_t ah0,ah1,ah2,ah3, al0,al1,al2,al3;                                \
    uint32_t bh0,bh1,bh2,bh3, bl0,bl1,bl2,bl3;                                \
    ldsm4t(ah0,ah1,ah2,ah3, aHi + (unsigned)(K0) * SAP);                      \
    ldsm4t(al0,al1,al2,al3, aHi + (unsigned)(K0) * SAP + 64u);                \
    ldsm4 (bh0,bh1,bh2,bh3, bHi + (unsigned)(K0) * 2u);                       \
    ldsm4 (bl0,bl1,bl2,bl3, bHi + (unsigned)(K0) * 2u + SWLO);                \
    mma16816(acc0, ah0,ah1,ah2,ah3, bh0,bh1);                                 \
    mma16816(acc1, ah0,ah1,ah2,ah3, bh2,bh3);                                 \
    mma16816(acc0, ah0,ah1,ah2,ah3, bl0,bl1);                                 \
    mma16816(acc1, ah0,ah1,ah2,ah3, bl2,bl3);                                 \
    mma16816(acc0, al0,al1,al2,al3, bh0,bh1);                                 \
    mma16816(acc1, al0,al1,al2,al3, bh2,bh3);                                 \
} while (0)

__global__ __launch_bounds__(NTHR, 1) void lstm_persistent(
    const float* __restrict__ x,    // [B,T,D]
    const float* __restrict__ Wx,   // [D,4H]
    const float* __restrict__ Wh,   // [H,4H]
    const float* __restrict__ bias, // [4H]
    float* __restrict__ out)        // [B,T,H]
{
    extern __shared__ char smem[];
    char* sA = smem + SW_BYTES;
    const unsigned int sWu = smem_u32(smem);
    const unsigned int sAu = smem_u32(sA);

    const int tid  = threadIdx.x;
    const int warp = tid >> 5;
    const int lane = tid & 31;
    const int mt   = warp & 1;               // m-tile (16 rows)
    const int nt   = warp >> 1;              // n-tile (16 gatecols = 4 units)
    const int ub   = blockIdx.x & 31;
    const int mb   = blockIdx.x >> 5;
    const int j0   = ub * 16;
    const int m0   = mb * 32;

    // ---- prologue: W -> bf16 hi/lo planes in smem, [n][k], n = u*4+g ----
    for (int i = 0; i < (64 * KTOT) / NTHR; ++i) {   // 136 iters
        int idx = i * NTHR + tid;
        int n = idx & 63;
        int k = idx >> 6;
        int col = (n & 3) * H_ + j0 + (n >> 2);
        float w = (k < H_) ? Wh[(size_t)k * G4 + col]
                           : Wx[(size_t)(k - H_) * G4 + col];
        __nv_bfloat16 hi = __float2bfloat16(w);
        float lo = w - __bfloat162float(hi);
        *(__nv_bfloat16*)(smem + n * SWP + k * 2) = hi;
        *(__nv_bfloat16*)(smem + SWLO + n * SWP + k * 2) = __float2bfloat16(lo);
    }

    // ---- prologue: transpose+convert this CTA's share of x into g_x ----
    {
        float* sX = (float*)sA;                      // scratch [32][33]
        for (int tt = ub; tt < T_; tt += 32) {
            float v[4];
            #pragma unroll
            for (int i = 0; i < 4; ++i) {
                int e = i * NTHR + tid;
                int m = e >> 5, d = e & 31;
                v[i] = x[(size_t)(m0 + m) * (T_ * D_) + (size_t)tt * D_ + d];
            }
            __syncthreads();
            #pragma unroll
            for (int i = 0; i < 4; ++i) {
                int e = i * NTHR + tid;
                int m = e >> 5, d = e & 31;
                sX[d * 33 + m] = v[i];
            }
            __syncthreads();
            unsigned char* gx = &g_x[mb][tt][0][0];
            #pragma unroll
            for (int i = 0; i < 4; ++i) {
                int e = i * NTHR + tid;
                int d = e >> 5, m = e & 31;
                float val = sX[d * 33 + m];
                __nv_bfloat16 hi = __float2bfloat16(val);
                float lo = val - __bfloat162float(hi);
                *(__nv_bfloat16*)(gx + d * 128 + m * 2) = hi;
                *(__nv_bfloat16*)(gx + d * 128 + 64 + m * 2) = __float2bfloat16(lo);
            }
            __syncthreads();
        }
    }

    // ---- zero A region; cross-CTA barrier for g_x; stage x(0) ----
    for (int i = tid; i < SA_BYTES / 4; i += NTHR) ((float*)sA)[i] = 0.f;
    __threadfence();
    __syncthreads();
    if (tid == 0) {
        atomicAdd(&g_init[mb], 1u);
        while (ld_acq(&g_init[mb]) < 32u) { }
    }
    __syncthreads();
    cp_async16(sAu + (unsigned)(512 + (tid >> 3)) * SAP + (tid & 7) * 16,
               &g_x[mb][0][0][0] + (tid >> 3) * 128 + (tid & 7) * 16);
    CP_COMMIT(); CP_WAIT(0);
    __syncthreads();

    // ---- per-lane fragment addresses ----
    const int li = lane & 7;
    const unsigned int aHi = sAu
        + (unsigned)((((lane >> 4) & 1) * 8 + li) * SAP)
        + (unsigned)((mt * 16 + ((lane >> 3) & 1) * 8) * 2);
    const unsigned int bHi = sWu
        + (unsigned)((nt * 16 + ((lane >> 4) & 1) * 8 + li) * SWP)
        + (unsigned)(((lane >> 3) & 1) * 16);

    // ---- per-lane epilogue constants (even lanes act) ----
    const int ul0 = nt * 4 + ((lane >> 1) & 1);
    const int jj0 = j0 + ul0;
    const int jj1 = jj0 + 2;
    const float bi0 = bias[jj0],      bf0 = bias[H_ + jj0];
    const float bg0 = bias[2*H_+jj0], bo0 = bias[3*H_+jj0];
    const float bi1 = bias[jj1],      bf1 = bias[H_ + jj1];
    const float bg1 = bias[2*H_+jj1], bo1 = bias[3*H_+jj1];
    float cS[4] = {0.f, 0.f, 0.f, 0.f};   // t0 rowA, t0 rowB, t1 rowA, t1 rowB

    for (int t = 0; t < T_; ++t) {
        float acc0[4] = {0.f, 0.f, 0.f, 0.f};
        float acc1[4] = {0.f, 0.f, 0.f, 0.f};

        if (t > 0) {
            const unsigned char* hsrc = &g_h[(t - 1) & 1][mb][0][0];
            const unsigned char* xsrc = &g_x[mb][t][0][0];
            // group X: x(t), 4KB
            cp_async16(sAu + (unsigned)(512 + (tid >> 3)) * SAP + (tid & 7) * 16,
                       xsrc + (tid >> 3) * 128 + (tid & 7) * 16);
            CP_COMMIT();
            // poll producer half 0, then issue group A (units 0-255)
            if (tid == 0) {
                unsigned tgt = 16u * (unsigned)t;
                while (ld_acq(&g_cnt[mb][0]) < tgt) { }
            }
            __syncthreads();
            #pragma unroll
            for (int i = 0; i < 8; ++i) {
                int g = i * NTHR + tid;
                int row = g >> 3, c = g & 7;
                cp_async16(sAu + (unsigned)row * SAP + c * 16,
                           hsrc + row * 128 + c * 16);
            }
            CP_COMMIT();
            // poll half 1, issue group B (units 256-511)
            if (tid == 0) {
                unsigned tgt = 16u * (unsigned)t;
                while (ld_acq(&g_cnt[mb][1]) < tgt) { }
            }
            __syncthreads();
            #pragma unroll
            for (int i = 0; i < 8; ++i) {
                int g = 2048 + i * NTHR + tid;
                int row = g >> 3, c = g & 7;
                cp_async16(sAu + (unsigned)row * SAP + c * 16,
                           hsrc + row * 128 + c * 16);
            }
            CP_COMMIT();
            CP_WAIT(2);                      // X landed
            __syncthreads();
        }

        // x chunk first (h-independent; covers group A flight)
        MMAIT(512); MMAIT(528);

        if (t > 0) { CP_WAIT(1); __syncthreads(); }
        #pragma unroll 2
        for (int k0 = 0; k0 < 256; k0 += 16) MMAIT(k0);

        if (t > 0) { CP_WAIT(0); __syncthreads(); }
        #pragma unroll 2
        for (int k0 = 256; k0 < 512; k0 += 16) MMAIT(k0);

        // ---- epilogue: pair lanes (i,f)<->(g,o) via shfl.xor(1) ----
        float s0 = __shfl_xor_sync(0xffffffffu, acc0[0], 1);
        float s1 = __shfl_xor_sync(0xffffffffu, acc0[1], 1);
        float s2 = __shfl_xor_sync(0xffffffffu, acc0[2], 1);
        float s3 = __shfl_xor_sync(0xffffffffu, acc0[3], 1);
        float s4 = __shfl_xor_sync(0xffffffffu, acc1[0], 1);
        float s5 = __shfl_xor_sync(0xffffffffu, acc1[1], 1);
        float s6 = __shfl_xor_sync(0xffffffffu, acc1[2], 1);
        float s7 = __shfl_xor_sync(0xffffffffu, acc1[3], 1);

        if (!(lane & 1)) {
            const int r    = lane >> 2;           // 0..7
            const int mloc = mt * 16 + r;
            unsigned char* gh0 = &g_h[t & 1][mb][jj0][0];
            unsigned char* gh1 = &g_h[t & 1][mb][jj1][0];
            float* o0 = out + (size_t)(m0 + mloc) * ((size_t)T_ * H_) + (size_t)t * H_;
            float* o1 = out + (size_t)(m0 + mloc + 8) * ((size_t)T_ * H_) + (size_t)t * H_;

            // tile0, unit jj0
            {
                float ig = fsig(acc0[0] + bi0), fg = fsig(acc0[1] + bf0);
                float gg = ftanh_(s0 + bg0),    og = fsig(s1 + bo0);
                cS[0] = fg * cS[0] + ig * gg;
                float h = og * ftanh_(cS[0]);
                o0[jj0] = h; store_h_bf(gh0, mloc, h);
            }
            {
                float ig = fsig(acc0[2] + bi0), fg = fsig(acc0[3] + bf0);
                float gg = ftanh_(s2 + bg0),    og = fsig(s3 + bo0);
                cS[1] = fg * cS[1] + ig * gg;
                float h = og * ftanh_(cS[1]);
                o1[jj0] = h; store_h_bf(gh0, mloc + 8, h);
            }
            // tile1, unit jj1
            {
                float ig = fsig(acc1[0] + bi1), fg = fsig(acc1[1] + bf1);
                float gg = ftanh_(s4 + bg1),    og = fsig(s5 + bo1);
                cS[2] = fg * cS[2] + ig * gg;
                float h = og * ftanh_(cS[2]);
                o0[jj1] = h; store_h_bf(gh1, mloc, h);
            }
            {
                float ig = fsig(acc1[2] + bi1), fg = fsig(acc1[3] + bf1);
                float gg = ftanh_(s6 + bg1),    og = fsig(s7 + bo1);
                cS[3] = fg * cS[3] + ig * gg;
                float h = og * ftanh_(cS[3]);
                o1[jj1] = h; store_h_bf(gh1, mloc + 8, h);
            }
        }
        __syncthreads();
        if (tid == 0) {
            __threadfence();
            atomicAdd(&g_cnt[mb][ub >> 4], 1u);
        }
    }
}

extern "C" void kernel_launch(void* const* d_in, const int* in_sizes, int n_in,
                              void* d_out, int out_size) {
    const float* x  = (const float*)d_in[0];
    const float* Wx = (const float*)d_in[1];
    const float* Wh = (const float*)d_in[2];
    const float* b  = (const float*)d_in[3];
    float* out = (float*)d_out;

    static bool attr_set = false;
    if (!attr_set) {
        cudaFuncSetAttribute(lstm_persistent,
                             cudaFuncAttributeMaxDynamicSharedMemorySize,
                             SMEM_BYTES);
        attr_set = true;
    }

    init_ctrl_kernel<<<1, 32>>>();
    lstm_persistent<<<NCTA, NTHR, SMEM_BYTES>>>(x, Wx, Wh, b, out);
}